// round 9
// baseline (speedup 1.0000x reference)
#include <cuda_runtime.h>
#include <math.h>

#define D_MODEL 1024
#define D_FF    2816
#define NHEADS  16
#define DK      64
#define BATCH   2
#define SEQ     2048
#define BSROWS  (BATCH*SEQ)   // 4096
#define EPSV    1e-5f

// ---------------- scratch (no cudaMalloc allowed) ----------------
static __device__ float g_h   [(size_t)BSROWS*D_MODEL];
static __device__ float g_q   [(size_t)BSROWS*D_MODEL];
static __device__ float g_k   [(size_t)BSROWS*D_MODEL];
static __device__ float g_v   [(size_t)BSROWS*D_MODEL];
static __device__ float g_attn[(size_t)BSROWS*D_MODEL];
static __device__ float g_y   [(size_t)BSROWS*D_MODEL];
static __device__ float g_u   [(size_t)BSROWS*D_FF];
static __device__ float g_g   [(size_t)BSROWS*D_FF];

// ---------------- RMSNorm: one block per row ----------------
__global__ void rmsnorm_k(const float* __restrict__ x, const float* __restrict__ gains,
                          float* __restrict__ o) {
    int row = blockIdx.x;
    const float* xr = x + (size_t)row * D_MODEL;
    float*       orow = o + (size_t)row * D_MODEL;
    float s = 0.f;
    for (int i = threadIdx.x; i < D_MODEL; i += 256) { float v = xr[i]; s += v * v; }
    #pragma unroll
    for (int off = 16; off; off >>= 1) s += __shfl_xor_sync(0xffffffffu, s, off);
    __shared__ float ws[8];
    __shared__ float rinv;
    if ((threadIdx.x & 31) == 0) ws[threadIdx.x >> 5] = s;
    __syncthreads();
    if (threadIdx.x == 0) {
        float t = 0.f;
        #pragma unroll
        for (int i = 0; i < 8; i++) t += ws[i];
        rinv = rsqrtf(t / (float)D_MODEL + EPSV);
    }
    __syncthreads();
    float r = rinv;
    for (int i = threadIdx.x; i < D_MODEL; i += 256)
        orow[i] = xr[i] * gains[i] * r;
}

// ---------------- NT GEMM: C[M,N] = A[M,K] * B[N,K]^T (+res) ----------------
// All of M, N divisible by 64; K divisible by 16. 64x64 tile, 256 threads, 4x4/thread.
__global__ __launch_bounds__(256) void gemm_nt(const float* __restrict__ A,
                                               const float* __restrict__ B,
                                               const float* __restrict__ res,
                                               float* __restrict__ C,
                                               int M, int N, int K) {
    __shared__ float As[64][17];
    __shared__ float Bs[64][17];
    const int t  = threadIdx.x;
    const int tx = t & 15, ty = t >> 4;
    const int lr = t >> 2;            // 0..63
    const int lc = (t & 3) << 2;      // 0,4,8,12
    const float* Ab = A + (size_t)(blockIdx.y * 64 + lr) * K + lc;
    const float* Bb = B + (size_t)(blockIdx.x * 64 + lr) * K + lc;
    float acc[4][4] = {};
    for (int k0 = 0; k0 < K; k0 += 16) {
        float4 a4 = *(const float4*)(Ab + k0);
        float4 b4 = *(const float4*)(Bb + k0);
        As[lr][lc+0] = a4.x; As[lr][lc+1] = a4.y; As[lr][lc+2] = a4.z; As[lr][lc+3] = a4.w;
        Bs[lr][lc+0] = b4.x; Bs[lr][lc+1] = b4.y; Bs[lr][lc+2] = b4.z; Bs[lr][lc+3] = b4.w;
        __syncthreads();
        #pragma unroll
        for (int kk = 0; kk < 16; kk++) {
            float a[4], b[4];
            #pragma unroll
            for (int i = 0; i < 4; i++) a[i] = As[ty * 4 + i][kk];
            #pragma unroll
            for (int j = 0; j < 4; j++) b[j] = Bs[tx * 4 + j][kk];
            #pragma unroll
            for (int i = 0; i < 4; i++)
                #pragma unroll
                for (int j = 0; j < 4; j++)
                    acc[i][j] += a[i] * b[j];
        }
        __syncthreads();
    }
    #pragma unroll
    for (int i = 0; i < 4; i++) {
        int r = blockIdx.y * 64 + ty * 4 + i;
        #pragma unroll
        for (int j = 0; j < 4; j++) {
            int c = blockIdx.x * 64 + tx * 4 + j;
            float vv = acc[i][j];
            if (res) vv += res[(size_t)r * N + c];
            C[(size_t)r * N + c] = vv;
        }
    }
}

// ---------------- RoPE in-place on [B,S,H,DK], interleaved pairs ----------------
__global__ void rope_k(float* __restrict__ x) {
    int idx = blockIdx.x * blockDim.x + threadIdx.x;     // over BSROWS*512 pairs
    if (idx >= BSROWS * (D_MODEL / 2)) return;
    int row  = idx >> 9;            // 512 pairs per row
    int p    = idx & 511;
    int s    = row & (SEQ - 1);
    int head = p >> 5;              // 32 pairs per head
    int j    = p & 31;
    float ex  = -(2.f * (float)j) / 64.f * logf(10000.f);
    float inv = expf(ex);
    float ang = (float)s * inv;
    float sn, cs; sincosf(ang, &sn, &cs);
    size_t base = (size_t)row * D_MODEL + head * 64 + 2 * j;
    float x0 = x[base], x1 = x[base + 1];
    x[base]     = x0 * cs - x1 * sn;
    x[base + 1] = x1 * cs + x0 * sn;
}

// ---------------- Flash attention (fp32, causal) ----------------
// grid: (SEQ/64, BATCH*NHEADS), block 256. Q tile 64 rows; iterate 64-key tiles.
// Thread layout: row = t>>2 (0..63), c4 = t&3; each thread owns 16 score cols and
// 16 output dims (d0 = c4*16).
#define ATTN_SMEM (4 * 64 * 65 * 4)
__global__ __launch_bounds__(256) void attn_k(const float* __restrict__ q,
                                              const float* __restrict__ k,
                                              const float* __restrict__ v,
                                              float* __restrict__ o) {
    extern __shared__ float sm[];
    float* Qs = sm;
    float* Ks = Qs + 64 * 65;
    float* Vs = Ks + 64 * 65;
    float* Ps = Vs + 64 * 65;
    const int bh = blockIdx.y;
    const int b  = bh / NHEADS, h = bh % NHEADS;
    const int q0 = blockIdx.x * 64;
    const int t  = threadIdx.x;
    const int row = t >> 2;
    const int c4  = t & 3;
    const int d0  = c4 * 16;
    const int kcb = c4 * 16;

    // load Q tile
    for (int i = t; i < 64 * 64; i += 256) {
        int r = i >> 6, d = i & 63;
        Qs[r * 65 + d] = q[((size_t)(b * SEQ + q0 + r)) * D_MODEL + h * 64 + d];
    }
    __syncthreads();

    float acc[16];
    #pragma unroll
    for (int i = 0; i < 16; i++) acc[i] = 0.f;
    float m = -1e30f, l = 0.f;
    const float scale = 0.125f;  // 1/sqrt(64)

    for (int k0 = 0; k0 <= q0; k0 += 64) {
        // load K,V tiles
        for (int i = t; i < 64 * 64; i += 256) {
            int r = i >> 6, d = i & 63;
            size_t gi = ((size_t)(b * SEQ + k0 + r)) * D_MODEL + h * 64 + d;
            Ks[r * 65 + d] = k[gi];
            Vs[r * 65 + d] = v[gi];
        }
        __syncthreads();

        // scores for 16 key columns
        float s[16];
        #pragma unroll
        for (int jj = 0; jj < 16; jj++) {
            float dot = 0.f;
            #pragma unroll 8
            for (int d = 0; d < 64; d++)
                dot += Qs[row * 65 + d] * Ks[(kcb + jj) * 65 + d];
            float sc = dot * scale;
            if (k0 + kcb + jj > q0 + row) sc = -1e30f;
            s[jj] = sc;
        }
        // row max across this thread + the 4 lanes sharing the row
        float mloc = s[0];
        #pragma unroll
        for (int jj = 1; jj < 16; jj++) mloc = fmaxf(mloc, s[jj]);
        mloc = fmaxf(mloc, __shfl_xor_sync(0xffffffffu, mloc, 1));
        mloc = fmaxf(mloc, __shfl_xor_sync(0xffffffffu, mloc, 2));
        float mnew = fmaxf(m, mloc);
        float corr = __expf(m - mnew);
        float psum = 0.f;
        #pragma unroll
        for (int jj = 0; jj < 16; jj++) {
            float p = __expf(s[jj] - mnew);
            Ps[row * 65 + kcb + jj] = p;
            psum += p;
        }
        psum += __shfl_xor_sync(0xffffffffu, psum, 1);
        psum += __shfl_xor_sync(0xffffffffu, psum, 2);
        l = l * corr + psum;
        m = mnew;
        #pragma unroll
        for (int i = 0; i < 16; i++) acc[i] *= corr;
        __syncwarp();   // Ps row written entirely within this warp
        // PV accumulate over this thread's 16 output dims
        for (int kc = 0; kc < 64; kc++) {
            float p = Ps[row * 65 + kc];
            #pragma unroll
            for (int dd = 0; dd < 16; dd++)
                acc[dd] += p * Vs[kc * 65 + d0 + dd];
        }
        __syncthreads();  // before K/V tile reload
    }

    float invl = 1.f / l;
    size_t obase = ((size_t)(b * SEQ + q0 + row)) * D_MODEL + h * 64 + d0;
    #pragma unroll
    for (int dd = 0; dd < 16; dd++) o[obase + dd] = acc[dd] * invl;
}

// ---------------- SwiGLU elementwise: u <- u*sigmoid(u)*g ----------------
__global__ void swiglu_k(float* __restrict__ u, const float* __restrict__ g) {
    size_t i = (size_t)blockIdx.x * blockDim.x + threadIdx.x;
    if (i < (size_t)BSROWS * D_FF) {
        float uv = u[i];
        float sg = 1.f / (1.f + __expf(-uv));
        u[i] = uv * sg * g[i];
    }
}

// ---------------- launch ----------------
extern "C" void kernel_launch(void* const* d_in, const int* in_sizes, int n_in,
                              void* d_out, int out_size) {
    const float* x      = (const float*)d_in[0];
    const float* gains1 = (const float*)d_in[1];
    const float* gains2 = (const float*)d_in[2];
    const float* WQ     = (const float*)d_in[3];
    const float* WK     = (const float*)d_in[4];
    const float* WV     = (const float*)d_in[5];
    const float* WO     = (const float*)d_in[6];
    const float* W1     = (const float*)d_in[7];
    const float* W2     = (const float*)d_in[8];
    const float* W3     = (const float*)d_in[9];
    float* out = (float*)d_out;

    float *h, *q, *k, *v, *attn, *y, *u, *g;
    cudaGetSymbolAddress((void**)&h,    g_h);
    cudaGetSymbolAddress((void**)&q,    g_q);
    cudaGetSymbolAddress((void**)&k,    g_k);
    cudaGetSymbolAddress((void**)&v,    g_v);
    cudaGetSymbolAddress((void**)&attn, g_attn);
    cudaGetSymbolAddress((void**)&y,    g_y);
    cudaGetSymbolAddress((void**)&u,    g_u);
    cudaGetSymbolAddress((void**)&g,    g_g);

    // 1. pre-attention RMSNorm
    rmsnorm_k<<<BSROWS, 256>>>(x, gains1, h);

    // 2. QKV projections
    dim3 gqkv(D_MODEL / 64, BSROWS / 64);
    gemm_nt<<<gqkv, 256>>>(h, WQ, nullptr, q, BSROWS, D_MODEL, D_MODEL);
    gemm_nt<<<gqkv, 256>>>(h, WK, nullptr, k, BSROWS, D_MODEL, D_MODEL);
    gemm_nt<<<gqkv, 256>>>(h, WV, nullptr, v, BSROWS, D_MODEL, D_MODEL);

    // 3. RoPE on q, k
    int ropeN = BSROWS * (D_MODEL / 2);
    rope_k<<<(ropeN + 255) / 256, 256>>>(q);
    rope_k<<<(ropeN + 255) / 256, 256>>>(k);

    // 4. causal flash attention
    cudaFuncSetAttribute(attn_k, cudaFuncAttributeMaxDynamicSharedMemorySize, ATTN_SMEM);
    attn_k<<<dim3(SEQ / 64, BATCH * NHEADS), 256, ATTN_SMEM>>>(q, k, v, attn);

    // 5. output projection + residual
    gemm_nt<<<gqkv, 256>>>(attn, WO, x, y, BSROWS, D_MODEL, D_MODEL);

    // 6. pre-FFN RMSNorm
    rmsnorm_k<<<BSROWS, 256>>>(y, gains2, h);

    // 7. FFN up/gate
    dim3 gff(D_FF / 64, BSROWS / 64);
    gemm_nt<<<gff, 256>>>(h, W1, nullptr, u, BSROWS, D_FF, D_MODEL);
    gemm_nt<<<gff, 256>>>(h, W3, nullptr, g, BSROWS, D_FF, D_MODEL);

    // 8. SwiGLU
    size_t nsw = (size_t)BSROWS * D_FF;
    swiglu_k<<<(int)((nsw + 255) / 256), 256>>>(u, g);

    // 9. down projection + residual -> out
    gemm_nt<<<gqkv, 256>>>(u, W2, y, out, BSROWS, D_MODEL, D_FF);
}

// round 10
// speedup vs baseline: 2.8737x; 2.8737x over previous
#include <cuda_runtime.h>
#include <math.h>

#define D_MODEL 1024
#define D_FF    2816
#define NHEADS  16
#define DK      64
#define BATCH   2
#define SEQ     2048
#define BSROWS  (BATCH*SEQ)   // 4096
#define EPSV    1e-5f

// ---------------- scratch (no cudaMalloc allowed) ----------------
static __device__ float g_h   [(size_t)BSROWS*D_MODEL];
static __device__ float g_q   [(size_t)BSROWS*D_MODEL];
static __device__ float g_k   [(size_t)BSROWS*D_MODEL];
static __device__ float g_v   [(size_t)BSROWS*D_MODEL];
static __device__ float g_attn[(size_t)BSROWS*D_MODEL];
static __device__ float g_y   [(size_t)BSROWS*D_MODEL];
static __device__ float g_u   [(size_t)BSROWS*D_FF];
static __device__ float g_g   [(size_t)BSROWS*D_FF];

// ---------------- RMSNorm: one block per row ----------------
__global__ void rmsnorm_k(const float* __restrict__ x, const float* __restrict__ gains,
                          float* __restrict__ o) {
    int row = blockIdx.x;
    const float* xr = x + (size_t)row * D_MODEL;
    float*       orow = o + (size_t)row * D_MODEL;
    float s = 0.f;
    for (int i = threadIdx.x; i < D_MODEL; i += 256) { float v = xr[i]; s += v * v; }
    #pragma unroll
    for (int off = 16; off; off >>= 1) s += __shfl_xor_sync(0xffffffffu, s, off);
    __shared__ float ws[8];
    __shared__ float rinv;
    if ((threadIdx.x & 31) == 0) ws[threadIdx.x >> 5] = s;
    __syncthreads();
    if (threadIdx.x == 0) {
        float t = 0.f;
        #pragma unroll
        for (int i = 0; i < 8; i++) t += ws[i];
        rinv = rsqrtf(t / (float)D_MODEL + EPSV);
    }
    __syncthreads();
    float r = rinv;
    for (int i = threadIdx.x; i < D_MODEL; i += 256)
        orow[i] = xr[i] * gains[i] * r;
}

// ---------------- TF32 tensor-core NT GEMM ----------------
// C[M,N] = A[M,K] * B[N,K]^T (+res). M,N % 128 == 0, K % 16 == 0.
// Block tile 128x128xBK16, 256 threads = 8 warps (2x4), warp tile 64x32.
// mma.sync.aligned.m16n8k8.row.col.f32.tf32.tf32.f32, explicit cvt.rna.
#define GLD 20   // smem row stride in words: (gid*20+tig) distinct mod 32 -> conflict-free frags

__device__ __forceinline__ unsigned f2tf32(float f) {
    unsigned u;
    asm("cvt.rna.tf32.f32 %0, %1;\n" : "=r"(u) : "f"(f));
    return u;
}

__device__ __forceinline__ void mma_tf32(float* d, const unsigned* a, const unsigned* b) {
    asm volatile(
        "mma.sync.aligned.m16n8k8.row.col.f32.tf32.tf32.f32 "
        "{%0,%1,%2,%3}, {%4,%5,%6,%7}, {%8,%9}, {%0,%1,%2,%3};\n"
        : "+f"(d[0]), "+f"(d[1]), "+f"(d[2]), "+f"(d[3])
        : "r"(a[0]), "r"(a[1]), "r"(a[2]), "r"(a[3]), "r"(b[0]), "r"(b[1]));
}

__global__ __launch_bounds__(256, 2) void gemm_tf32(const float* __restrict__ A,
                                                    const float* __restrict__ B,
                                                    const float* __restrict__ res,
                                                    float* __restrict__ C,
                                                    int M, int N, int K) {
    __shared__ unsigned As[128 * GLD];
    __shared__ unsigned Bs[128 * GLD];
    const int t    = threadIdx.x;
    const int warp = t >> 5, lane = t & 31;
    const int gid  = lane >> 2, tig = lane & 3;
    const int wm   = (warp >> 2) * 64;   // 0 / 64
    const int wn   = (warp & 3) * 32;    // 0..96
    const int bm   = blockIdx.y * 128, bn = blockIdx.x * 128;

    const int lr = t >> 2;          // 0..63
    const int lc = (t & 3) * 4;     // 0,4,8,12
    const float* Ag = A + (size_t)(bm + lr) * K + lc;
    const float* Bg = B + (size_t)(bn + lr) * K + lc;

    float4 pa0 = *(const float4*)(Ag);
    float4 pa1 = *(const float4*)(Ag + (size_t)64 * K);
    float4 pb0 = *(const float4*)(Bg);
    float4 pb1 = *(const float4*)(Bg + (size_t)64 * K);

    float acc[4][4][4];
    #pragma unroll
    for (int i = 0; i < 4; i++)
        #pragma unroll
        for (int j = 0; j < 4; j++)
            #pragma unroll
            for (int r = 0; r < 4; r++) acc[i][j][r] = 0.f;

    for (int k0 = 0; k0 < K; k0 += 16) {
        // stage current tile into smem (converted to tf32)
        uint4 sa0 = make_uint4(f2tf32(pa0.x), f2tf32(pa0.y), f2tf32(pa0.z), f2tf32(pa0.w));
        uint4 sa1 = make_uint4(f2tf32(pa1.x), f2tf32(pa1.y), f2tf32(pa1.z), f2tf32(pa1.w));
        uint4 sb0 = make_uint4(f2tf32(pb0.x), f2tf32(pb0.y), f2tf32(pb0.z), f2tf32(pb0.w));
        uint4 sb1 = make_uint4(f2tf32(pb1.x), f2tf32(pb1.y), f2tf32(pb1.z), f2tf32(pb1.w));
        *(uint4*)&As[lr * GLD + lc]        = sa0;
        *(uint4*)&As[(lr + 64) * GLD + lc] = sa1;
        *(uint4*)&Bs[lr * GLD + lc]        = sb0;
        *(uint4*)&Bs[(lr + 64) * GLD + lc] = sb1;
        __syncthreads();
        // prefetch next tile while computing
        if (k0 + 16 < K) {
            pa0 = *(const float4*)(Ag + k0 + 16);
            pa1 = *(const float4*)(Ag + (size_t)64 * K + k0 + 16);
            pb0 = *(const float4*)(Bg + k0 + 16);
            pb1 = *(const float4*)(Bg + (size_t)64 * K + k0 + 16);
        }
        #pragma unroll
        for (int ks = 0; ks < 2; ks++) {
            const int ko = ks * 8;
            unsigned af[4][4];
            #pragma unroll
            for (int mt = 0; mt < 4; mt++) {
                int r = wm + mt * 16 + gid;
                af[mt][0] = As[r * GLD + ko + tig];
                af[mt][1] = As[(r + 8) * GLD + ko + tig];
                af[mt][2] = As[r * GLD + ko + tig + 4];
                af[mt][3] = As[(r + 8) * GLD + ko + tig + 4];
            }
            unsigned bf[4][2];
            #pragma unroll
            for (int nt = 0; nt < 4; nt++) {
                int c = wn + nt * 8 + gid;
                bf[nt][0] = Bs[c * GLD + ko + tig];
                bf[nt][1] = Bs[c * GLD + ko + tig + 4];
            }
            #pragma unroll
            for (int mt = 0; mt < 4; mt++)
                #pragma unroll
                for (int nt = 0; nt < 4; nt++)
                    mma_tf32(acc[mt][nt], af[mt], bf[nt]);
        }
        __syncthreads();
    }

    // epilogue
    #pragma unroll
    for (int mt = 0; mt < 4; mt++) {
        int r0 = bm + wm + mt * 16 + gid;
        #pragma unroll
        for (int nt = 0; nt < 4; nt++) {
            int c0 = bn + wn + nt * 8 + tig * 2;
            float2 v0 = make_float2(acc[mt][nt][0], acc[mt][nt][1]);
            float2 v1 = make_float2(acc[mt][nt][2], acc[mt][nt][3]);
            if (res) {
                float2 r0v = *(const float2*)&res[(size_t)r0 * N + c0];
                float2 r1v = *(const float2*)&res[(size_t)(r0 + 8) * N + c0];
                v0.x += r0v.x; v0.y += r0v.y;
                v1.x += r1v.x; v1.y += r1v.y;
            }
            *(float2*)&C[(size_t)r0 * N + c0]       = v0;
            *(float2*)&C[(size_t)(r0 + 8) * N + c0] = v1;
        }
    }
}

// ---------------- RoPE in-place on [B,S,H,DK], interleaved pairs ----------------
__global__ void rope_k(float* __restrict__ x) {
    int idx = blockIdx.x * blockDim.x + threadIdx.x;
    if (idx >= BSROWS * (D_MODEL / 2)) return;
    int row  = idx >> 9;
    int p    = idx & 511;
    int s    = row & (SEQ - 1);
    int head = p >> 5;
    int j    = p & 31;
    float ex  = -(2.f * (float)j) / 64.f * logf(10000.f);
    float inv = expf(ex);
    float ang = (float)s * inv;
    float sn, cs; sincosf(ang, &sn, &cs);
    size_t base = (size_t)row * D_MODEL + head * 64 + 2 * j;
    float x0 = x[base], x1 = x[base + 1];
    x[base]     = x0 * cs - x1 * sn;
    x[base + 1] = x1 * cs + x0 * sn;
}

// ---------------- Flash attention (fp32, causal), vectorized ----------------
// grid: (SEQ/64, BATCH*NHEADS), block 256. Q tile 64 rows, 64-key tiles.
// Thread (row = t>>2, c4 = t&3): score cols {c4+4*jj}, output dims {(c4+4i)*4 .. +3}.
#define ASTR 17   // float4 row stride (68 floats)
#define ATTN_SMEM (4 * 64 * ASTR * 16)
__global__ __launch_bounds__(256) void attn_k(const float* __restrict__ q,
                                              const float* __restrict__ k,
                                              const float* __restrict__ v,
                                              float* __restrict__ o) {
    extern __shared__ float sm[];
    float4* Qs = (float4*)sm;
    float4* Ks = Qs + 64 * ASTR;
    float4* Vs = Ks + 64 * ASTR;
    float*  Ps = (float*)(Vs + 64 * ASTR);   // 64 x 68 floats
    const int bh = blockIdx.y;
    const int b  = bh / NHEADS, h = bh % NHEADS;
    const int q0 = blockIdx.x * 64;
    const int t  = threadIdx.x;
    const int row = t >> 2;
    const int c4  = t & 3;

    // stage Q tile, then hoist own row to registers (constant across key tiles)
    for (int i = t; i < 64 * 16; i += 256) {
        int r = i >> 4, d4 = i & 15;
        Qs[r * ASTR + d4] =
            *(const float4*)&q[((size_t)(b * SEQ + q0 + r)) * D_MODEL + h * 64 + d4 * 4];
    }
    __syncthreads();
    float4 qr[16];
    #pragma unroll
    for (int d4 = 0; d4 < 16; d4++) qr[d4] = Qs[row * ASTR + d4];

    float4 acc4[4];
    #pragma unroll
    for (int i = 0; i < 4; i++) acc4[i] = make_float4(0.f, 0.f, 0.f, 0.f);
    float m = -1e30f, l = 0.f;
    const float scale = 0.125f;  // 1/sqrt(64)

    for (int k0 = 0; k0 <= q0; k0 += 64) {
        __syncthreads();   // previous tile fully consumed
        for (int i = t; i < 64 * 16; i += 256) {
            int r = i >> 4, d4 = i & 15;
            size_t gi = ((size_t)(b * SEQ + k0 + r)) * D_MODEL + h * 64 + d4 * 4;
            Ks[r * ASTR + d4] = *(const float4*)&k[gi];
            Vs[r * ASTR + d4] = *(const float4*)&v[gi];
        }
        __syncthreads();

        float s[16];
        #pragma unroll
        for (int jj = 0; jj < 16; jj++) {
            int col = c4 + 4 * jj;
            const float4* kp = Ks + col * ASTR;
            float dot = 0.f;
            #pragma unroll
            for (int d4 = 0; d4 < 16; d4++) {
                float4 kk = kp[d4];
                dot += qr[d4].x * kk.x + qr[d4].y * kk.y + qr[d4].z * kk.z + qr[d4].w * kk.w;
            }
            s[jj] = (k0 + col > q0 + row) ? -1e30f : dot * scale;
        }
        float mloc = s[0];
        #pragma unroll
        for (int jj = 1; jj < 16; jj++) mloc = fmaxf(mloc, s[jj]);
        mloc = fmaxf(mloc, __shfl_xor_sync(0xffffffffu, mloc, 1));
        mloc = fmaxf(mloc, __shfl_xor_sync(0xffffffffu, mloc, 2));
        float mnew = fmaxf(m, mloc);
        float corr = __expf(m - mnew);
        float psum = 0.f;
        #pragma unroll
        for (int jj = 0; jj < 16; jj++) {
            float p = __expf(s[jj] - mnew);
            Ps[row * 68 + c4 + 4 * jj] = p;
            psum += p;
        }
        psum += __shfl_xor_sync(0xffffffffu, psum, 1);
        psum += __shfl_xor_sync(0xffffffffu, psum, 2);
        l = l * corr + psum;
        m = mnew;
        #pragma unroll
        for (int i = 0; i < 4; i++) {
            acc4[i].x *= corr; acc4[i].y *= corr; acc4[i].z *= corr; acc4[i].w *= corr;
        }
        __syncwarp();   // Ps row produced entirely within this quad/warp

        for (int kc = 0; kc < 64; kc++) {
            float p = Ps[row * 68 + kc];
            const float4* vp = Vs + kc * ASTR;
            #pragma unroll
            for (int i = 0; i < 4; i++) {
                float4 vv = vp[c4 + 4 * i];
                acc4[i].x += p * vv.x; acc4[i].y += p * vv.y;
                acc4[i].z += p * vv.z; acc4[i].w += p * vv.w;
            }
        }
    }

    float invl = 1.f / l;
    size_t obase = ((size_t)(b * SEQ + q0 + row)) * D_MODEL + h * 64;
    #pragma unroll
    for (int i = 0; i < 4; i++) {
        float4 ov = make_float4(acc4[i].x * invl, acc4[i].y * invl,
                                acc4[i].z * invl, acc4[i].w * invl);
        *(float4*)&o[obase + (c4 + 4 * i) * 4] = ov;
    }
}

// ---------------- SwiGLU elementwise: u <- u*sigmoid(u)*g ----------------
__global__ void swiglu_k(float* __restrict__ u, const float* __restrict__ g) {
    size_t i = (size_t)blockIdx.x * blockDim.x + threadIdx.x;
    if (i < (size_t)BSROWS * D_FF) {
        float uv = u[i];
        float sg = 1.f / (1.f + __expf(-uv));
        u[i] = uv * sg * g[i];
    }
}

// ---------------- launch ----------------
extern "C" void kernel_launch(void* const* d_in, const int* in_sizes, int n_in,
                              void* d_out, int out_size) {
    const float* x      = (const float*)d_in[0];
    const float* gains1 = (const float*)d_in[1];
    const float* gains2 = (const float*)d_in[2];
    const float* WQ     = (const float*)d_in[3];
    const float* WK     = (const float*)d_in[4];
    const float* WV     = (const float*)d_in[5];
    const float* WO     = (const float*)d_in[6];
    const float* W1     = (const float*)d_in[7];
    const float* W2     = (const float*)d_in[8];
    const float* W3     = (const float*)d_in[9];
    float* out = (float*)d_out;

    float *h, *q, *k, *v, *attn, *y, *u, *g;
    cudaGetSymbolAddress((void**)&h,    g_h);
    cudaGetSymbolAddress((void**)&q,    g_q);
    cudaGetSymbolAddress((void**)&k,    g_k);
    cudaGetSymbolAddress((void**)&v,    g_v);
    cudaGetSymbolAddress((void**)&attn, g_attn);
    cudaGetSymbolAddress((void**)&y,    g_y);
    cudaGetSymbolAddress((void**)&u,    g_u);
    cudaGetSymbolAddress((void**)&g,    g_g);

    // 1. pre-attention RMSNorm
    rmsnorm_k<<<BSROWS, 256>>>(x, gains1, h);

    // 2. QKV projections (TF32 tensor cores)
    dim3 gqkv(D_MODEL / 128, BSROWS / 128);
    gemm_tf32<<<gqkv, 256>>>(h, WQ, nullptr, q, BSROWS, D_MODEL, D_MODEL);
    gemm_tf32<<<gqkv, 256>>>(h, WK, nullptr, k, BSROWS, D_MODEL, D_MODEL);
    gemm_tf32<<<gqkv, 256>>>(h, WV, nullptr, v, BSROWS, D_MODEL, D_MODEL);

    // 3. RoPE on q, k
    int ropeN = BSROWS * (D_MODEL / 2);
    rope_k<<<(ropeN + 255) / 256, 256>>>(q);
    rope_k<<<(ropeN + 255) / 256, 256>>>(k);

    // 4. causal flash attention
    cudaFuncSetAttribute(attn_k, cudaFuncAttributeMaxDynamicSharedMemorySize, ATTN_SMEM);
    attn_k<<<dim3(SEQ / 64, BATCH * NHEADS), 256, ATTN_SMEM>>>(q, k, v, attn);

    // 5. output projection + residual
    gemm_tf32<<<gqkv, 256>>>(attn, WO, x, y, BSROWS, D_MODEL, D_MODEL);

    // 6. pre-FFN RMSNorm
    rmsnorm_k<<<BSROWS, 256>>>(y, gains2, h);

    // 7. FFN up/gate
    dim3 gff(D_FF / 128, BSROWS / 128);
    gemm_tf32<<<gff, 256>>>(h, W1, nullptr, u, BSROWS, D_FF, D_MODEL);
    gemm_tf32<<<gff, 256>>>(h, W3, nullptr, g, BSROWS, D_FF, D_MODEL);

    // 8. SwiGLU
    size_t nsw = (size_t)BSROWS * D_FF;
    swiglu_k<<<(int)((nsw + 255) / 256), 256>>>(u, g);

    // 9. down projection + residual -> out
    gemm_tf32<<<gqkv, 256>>>(u, W2, y, out, BSROWS, D_MODEL, D_FF);
}

// round 11
// speedup vs baseline: 5.0231x; 1.7480x over previous
#include <cuda_runtime.h>
#include <math.h>

#define D_MODEL 1024
#define D_FF    2816
#define NHEADS  16
#define DK      64
#define BATCH   2
#define SEQ     2048
#define BSROWS  (BATCH*SEQ)   // 4096
#define EPSV    1e-5f

// ---------------- scratch (no cudaMalloc allowed) ----------------
static __device__ float g_h   [(size_t)BSROWS*D_MODEL];
static __device__ float g_q   [(size_t)BSROWS*D_MODEL];
static __device__ float g_k   [(size_t)BSROWS*D_MODEL];
static __device__ float g_v   [(size_t)BSROWS*D_MODEL];
static __device__ float g_attn[(size_t)BSROWS*D_MODEL];
static __device__ float g_y   [(size_t)BSROWS*D_MODEL];
static __device__ float g_u   [(size_t)BSROWS*D_FF];
static __device__ float g_g   [(size_t)BSROWS*D_FF];

// ---------------- common MMA helpers ----------------
__device__ __forceinline__ unsigned f2tf32(float f) {
    unsigned u;
    asm("cvt.rna.tf32.f32 %0, %1;\n" : "=r"(u) : "f"(f));
    return u;
}

__device__ __forceinline__ void mma_tf32(float* d, const unsigned* a, const unsigned* b) {
    asm volatile(
        "mma.sync.aligned.m16n8k8.row.col.f32.tf32.tf32.f32 "
        "{%0,%1,%2,%3}, {%4,%5,%6,%7}, {%8,%9}, {%0,%1,%2,%3};\n"
        : "+f"(d[0]), "+f"(d[1]), "+f"(d[2]), "+f"(d[3])
        : "r"(a[0]), "r"(a[1]), "r"(a[2]), "r"(a[3]), "r"(b[0]), "r"(b[1]));
}

// ---------------- RMSNorm: one block per row ----------------
__global__ void rmsnorm_k(const float* __restrict__ x, const float* __restrict__ gains,
                          float* __restrict__ o) {
    int row = blockIdx.x;
    const float* xr = x + (size_t)row * D_MODEL;
    float*       orow = o + (size_t)row * D_MODEL;
    float s = 0.f;
    for (int i = threadIdx.x; i < D_MODEL; i += 256) { float v = xr[i]; s += v * v; }
    #pragma unroll
    for (int off = 16; off; off >>= 1) s += __shfl_xor_sync(0xffffffffu, s, off);
    __shared__ float ws[8];
    __shared__ float rinv;
    if ((threadIdx.x & 31) == 0) ws[threadIdx.x >> 5] = s;
    __syncthreads();
    if (threadIdx.x == 0) {
        float t = 0.f;
        #pragma unroll
        for (int i = 0; i < 8; i++) t += ws[i];
        rinv = rsqrtf(t / (float)D_MODEL + EPSV);
    }
    __syncthreads();
    float r = rinv;
    for (int i = threadIdx.x; i < D_MODEL; i += 256)
        orow[i] = xr[i] * gains[i] * r;
}

// ---------------- TF32 tensor-core NT GEMM (unchanged from R10) ----------------
#define GLD 20

__global__ __launch_bounds__(256, 2) void gemm_tf32(const float* __restrict__ A,
                                                    const float* __restrict__ B,
                                                    const float* __restrict__ res,
                                                    float* __restrict__ C,
                                                    int M, int N, int K) {
    __shared__ unsigned As[128 * GLD];
    __shared__ unsigned Bs[128 * GLD];
    const int t    = threadIdx.x;
    const int warp = t >> 5, lane = t & 31;
    const int gid  = lane >> 2, tig = lane & 3;
    const int wm   = (warp >> 2) * 64;
    const int wn   = (warp & 3) * 32;
    const int bm   = blockIdx.y * 128, bn = blockIdx.x * 128;

    const int lr = t >> 2;
    const int lc = (t & 3) * 4;
    const float* Ag = A + (size_t)(bm + lr) * K + lc;
    const float* Bg = B + (size_t)(bn + lr) * K + lc;

    float4 pa0 = *(const float4*)(Ag);
    float4 pa1 = *(const float4*)(Ag + (size_t)64 * K);
    float4 pb0 = *(const float4*)(Bg);
    float4 pb1 = *(const float4*)(Bg + (size_t)64 * K);

    float acc[4][4][4];
    #pragma unroll
    for (int i = 0; i < 4; i++)
        #pragma unroll
        for (int j = 0; j < 4; j++)
            #pragma unroll
            for (int r = 0; r < 4; r++) acc[i][j][r] = 0.f;

    for (int k0 = 0; k0 < K; k0 += 16) {
        uint4 sa0 = make_uint4(f2tf32(pa0.x), f2tf32(pa0.y), f2tf32(pa0.z), f2tf32(pa0.w));
        uint4 sa1 = make_uint4(f2tf32(pa1.x), f2tf32(pa1.y), f2tf32(pa1.z), f2tf32(pa1.w));
        uint4 sb0 = make_uint4(f2tf32(pb0.x), f2tf32(pb0.y), f2tf32(pb0.z), f2tf32(pb0.w));
        uint4 sb1 = make_uint4(f2tf32(pb1.x), f2tf32(pb1.y), f2tf32(pb1.z), f2tf32(pb1.w));
        *(uint4*)&As[lr * GLD + lc]        = sa0;
        *(uint4*)&As[(lr + 64) * GLD + lc] = sa1;
        *(uint4*)&Bs[lr * GLD + lc]        = sb0;
        *(uint4*)&Bs[(lr + 64) * GLD + lc] = sb1;
        __syncthreads();
        if (k0 + 16 < K) {
            pa0 = *(const float4*)(Ag + k0 + 16);
            pa1 = *(const float4*)(Ag + (size_t)64 * K + k0 + 16);
            pb0 = *(const float4*)(Bg + k0 + 16);
            pb1 = *(const float4*)(Bg + (size_t)64 * K + k0 + 16);
        }
        #pragma unroll
        for (int ks = 0; ks < 2; ks++) {
            const int ko = ks * 8;
            unsigned af[4][4];
            #pragma unroll
            for (int mt = 0; mt < 4; mt++) {
                int r = wm + mt * 16 + gid;
                af[mt][0] = As[r * GLD + ko + tig];
                af[mt][1] = As[(r + 8) * GLD + ko + tig];
                af[mt][2] = As[r * GLD + ko + tig + 4];
                af[mt][3] = As[(r + 8) * GLD + ko + tig + 4];
            }
            unsigned bf[4][2];
            #pragma unroll
            for (int nt = 0; nt < 4; nt++) {
                int c = wn + nt * 8 + gid;
                bf[nt][0] = Bs[c * GLD + ko + tig];
                bf[nt][1] = Bs[c * GLD + ko + tig + 4];
            }
            #pragma unroll
            for (int mt = 0; mt < 4; mt++)
                #pragma unroll
                for (int nt = 0; nt < 4; nt++)
                    mma_tf32(acc[mt][nt], af[mt], bf[nt]);
        }
        __syncthreads();
    }

    #pragma unroll
    for (int mt = 0; mt < 4; mt++) {
        int r0 = bm + wm + mt * 16 + gid;
        #pragma unroll
        for (int nt = 0; nt < 4; nt++) {
            int c0 = bn + wn + nt * 8 + tig * 2;
            float2 v0 = make_float2(acc[mt][nt][0], acc[mt][nt][1]);
            float2 v1 = make_float2(acc[mt][nt][2], acc[mt][nt][3]);
            if (res) {
                float2 r0v = *(const float2*)&res[(size_t)r0 * N + c0];
                float2 r1v = *(const float2*)&res[(size_t)(r0 + 8) * N + c0];
                v0.x += r0v.x; v0.y += r0v.y;
                v1.x += r1v.x; v1.y += r1v.y;
            }
            *(float2*)&C[(size_t)r0 * N + c0]       = v0;
            *(float2*)&C[(size_t)(r0 + 8) * N + c0] = v1;
        }
    }
}

// ---------------- RoPE in-place on [B,S,H,DK], interleaved pairs ----------------
__global__ void rope_k(float* __restrict__ x) {
    int idx = blockIdx.x * blockDim.x + threadIdx.x;
    if (idx >= BSROWS * (D_MODEL / 2)) return;
    int row  = idx >> 9;
    int p    = idx & 511;
    int s    = row & (SEQ - 1);
    int head = p >> 5;
    int j    = p & 31;
    float ex  = -(2.f * (float)j) / 64.f * logf(10000.f);
    float inv = expf(ex);
    float ang = (float)s * inv;
    float sn, cs; sincosf(ang, &sn, &cs);
    size_t base = (size_t)row * D_MODEL + head * 64 + 2 * j;
    float x0 = x[base], x1 = x[base + 1];
    x[base]     = x0 * cs - x1 * sn;
    x[base + 1] = x1 * cs + x0 * sn;
}

// ---------------- Flash attention, TF32 tensor cores ----------------
// Q tile 128 rows x 64, 8 warps (16 rows each), 64-key tiles.
// Q frags in registers across all tiles. K smem [key][dk]; V smem transposed [dk][key].
// S = Q K^T via mma (m16n8k8), online softmax on fragments, P via smem roundtrip
// (reusing Q region; per-warp-private rows), O = P V via mma.
#define ASTR 68
#define ATTN_SMEM ((128 * ASTR + 2 * 64 * ASTR) * 4)
__global__ __launch_bounds__(256) void attn_mma(const float* __restrict__ q,
                                                const float* __restrict__ k,
                                                const float* __restrict__ v,
                                                float* __restrict__ o) {
    extern __shared__ unsigned sm_u[];
    unsigned* Qs = sm_u;                 // 128 x ASTR, reused as Ps after Q frag load
    unsigned* Ps = sm_u;
    unsigned* Ks = sm_u + 128 * ASTR;    // 64 x ASTR
    unsigned* Vs = Ks + 64 * ASTR;       // 64 x ASTR (transposed: [dk][key])

    const int bh = blockIdx.y;
    const int b  = bh / NHEADS, h = bh % NHEADS;
    const int q0 = blockIdx.x * 128;
    const int t  = threadIdx.x;
    const int warp = t >> 5, lane = t & 31;
    const int gid = lane >> 2, tig = lane & 3;
    const int wr  = warp * 16;

    // stage Q tile (scaled by 1/sqrt(dk), tf32)
    for (int i = t; i < 128 * 16; i += 256) {
        int r = i >> 4, d4 = i & 15;
        float4 qv = *(const float4*)&q[((size_t)(b * SEQ + q0 + r)) * D_MODEL + h * 64 + d4 * 4];
        *(uint4*)&Qs[r * ASTR + d4 * 4] =
            make_uint4(f2tf32(qv.x * 0.125f), f2tf32(qv.y * 0.125f),
                       f2tf32(qv.z * 0.125f), f2tf32(qv.w * 0.125f));
    }
    __syncthreads();

    // Q fragments in registers (rows wr+gid, wr+gid+8 — warp-private)
    unsigned qa[8][4];
    #pragma unroll
    for (int ks = 0; ks < 8; ks++) {
        qa[ks][0] = Qs[(wr + gid) * ASTR + ks * 8 + tig];
        qa[ks][1] = Qs[(wr + gid + 8) * ASTR + ks * 8 + tig];
        qa[ks][2] = Qs[(wr + gid) * ASTR + ks * 8 + tig + 4];
        qa[ks][3] = Qs[(wr + gid + 8) * ASTR + ks * 8 + tig + 4];
    }

    float oacc[8][4];
    #pragma unroll
    for (int nt = 0; nt < 8; nt++)
        #pragma unroll
        for (int e = 0; e < 4; e++) oacc[nt][e] = 0.f;
    float m0 = -1e30f, m1 = -1e30f, l0 = 0.f, l1 = 0.f;

    const int r0 = q0 + wr + gid;
    const int r1 = r0 + 8;
    const int ntiles = q0 / 64 + 2;

    for (int kt = 0; kt < ntiles; kt++) {
        const int k0 = kt * 64;
        __syncthreads();   // previous tile fully consumed (covers Ps too)
        // stage K [key][dk] + V transposed [dk][key], both tf32
        for (int i = t; i < 64 * 16; i += 256) {
            int r = i >> 4, d4 = i & 15;
            size_t gi = ((size_t)(b * SEQ + k0 + r)) * D_MODEL + h * 64 + d4 * 4;
            float4 kv = *(const float4*)&k[gi];
            *(uint4*)&Ks[r * ASTR + d4 * 4] =
                make_uint4(f2tf32(kv.x), f2tf32(kv.y), f2tf32(kv.z), f2tf32(kv.w));
            float4 vv = *(const float4*)&v[gi];
            Vs[(d4 * 4 + 0) * ASTR + r] = f2tf32(vv.x);
            Vs[(d4 * 4 + 1) * ASTR + r] = f2tf32(vv.y);
            Vs[(d4 * 4 + 2) * ASTR + r] = f2tf32(vv.z);
            Vs[(d4 * 4 + 3) * ASTR + r] = f2tf32(vv.w);
        }
        __syncthreads();

        // S = Q K^T
        float sacc[8][4];
        #pragma unroll
        for (int nt = 0; nt < 8; nt++) {
            sacc[nt][0] = sacc[nt][1] = sacc[nt][2] = sacc[nt][3] = 0.f;
            #pragma unroll
            for (int ks = 0; ks < 8; ks++) {
                unsigned kb[2];
                kb[0] = Ks[(nt * 8 + gid) * ASTR + ks * 8 + tig];
                kb[1] = Ks[(nt * 8 + gid) * ASTR + ks * 8 + tig + 4];
                mma_tf32(sacc[nt], qa[ks], kb);
            }
        }

        // causal mask (only diagonal-overlapping tiles)
        if (k0 + 63 > q0) {
            #pragma unroll
            for (int nt = 0; nt < 8; nt++) {
                int c0 = k0 + nt * 8 + tig * 2;
                if (c0     > r0) sacc[nt][0] = -1e30f;
                if (c0 + 1 > r0) sacc[nt][1] = -1e30f;
                if (c0     > r1) sacc[nt][2] = -1e30f;
                if (c0 + 1 > r1) sacc[nt][3] = -1e30f;
            }
        }

        // online softmax on fragments
        float m0loc = -1e30f, m1loc = -1e30f;
        #pragma unroll
        for (int nt = 0; nt < 8; nt++) {
            m0loc = fmaxf(m0loc, fmaxf(sacc[nt][0], sacc[nt][1]));
            m1loc = fmaxf(m1loc, fmaxf(sacc[nt][2], sacc[nt][3]));
        }
        m0loc = fmaxf(m0loc, __shfl_xor_sync(0xffffffffu, m0loc, 1));
        m0loc = fmaxf(m0loc, __shfl_xor_sync(0xffffffffu, m0loc, 2));
        m1loc = fmaxf(m1loc, __shfl_xor_sync(0xffffffffu, m1loc, 1));
        m1loc = fmaxf(m1loc, __shfl_xor_sync(0xffffffffu, m1loc, 2));
        float mn0 = fmaxf(m0, m0loc), mn1 = fmaxf(m1, m1loc);
        float corr0 = __expf(m0 - mn0), corr1 = __expf(m1 - mn1);
        float ps0 = 0.f, ps1 = 0.f;
        #pragma unroll
        for (int nt = 0; nt < 8; nt++) {
            float p0 = __expf(sacc[nt][0] - mn0);
            float p1 = __expf(sacc[nt][1] - mn0);
            float p2 = __expf(sacc[nt][2] - mn1);
            float p3 = __expf(sacc[nt][3] - mn1);
            ps0 += p0 + p1; ps1 += p2 + p3;
            *(uint2*)&Ps[(wr + gid) * ASTR + nt * 8 + tig * 2] =
                make_uint2(f2tf32(p0), f2tf32(p1));
            *(uint2*)&Ps[(wr + gid + 8) * ASTR + nt * 8 + tig * 2] =
                make_uint2(f2tf32(p2), f2tf32(p3));
        }
        ps0 += __shfl_xor_sync(0xffffffffu, ps0, 1);
        ps0 += __shfl_xor_sync(0xffffffffu, ps0, 2);
        ps1 += __shfl_xor_sync(0xffffffffu, ps1, 1);
        ps1 += __shfl_xor_sync(0xffffffffu, ps1, 2);
        l0 = l0 * corr0 + ps0;
        l1 = l1 * corr1 + ps1;
        m0 = mn0; m1 = mn1;
        #pragma unroll
        for (int nt = 0; nt < 8; nt++) {
            oacc[nt][0] *= corr0; oacc[nt][1] *= corr0;
            oacc[nt][2] *= corr1; oacc[nt][3] *= corr1;
        }
        __syncwarp();   // Ps rows are warp-private; order cross-lane store->load

        // O += P V   (A = P from smem, B = V^T frags)
        #pragma unroll
        for (int ks = 0; ks < 8; ks++) {
            unsigned pa[4];
            pa[0] = Ps[(wr + gid) * ASTR + ks * 8 + tig];
            pa[1] = Ps[(wr + gid + 8) * ASTR + ks * 8 + tig];
            pa[2] = Ps[(wr + gid) * ASTR + ks * 8 + tig + 4];
            pa[3] = Ps[(wr + gid + 8) * ASTR + ks * 8 + tig + 4];
            #pragma unroll
            for (int nt = 0; nt < 8; nt++) {
                unsigned vb[2];
                vb[0] = Vs[(nt * 8 + gid) * ASTR + ks * 8 + tig];
                vb[1] = Vs[(nt * 8 + gid) * ASTR + ks * 8 + tig + 4];
                mma_tf32(oacc[nt], pa, vb);
            }
        }
    }

    // epilogue
    float i0 = 1.f / l0, i1 = 1.f / l1;
    size_t ob0 = ((size_t)(b * SEQ + r0)) * D_MODEL + h * 64;
    size_t ob1 = ((size_t)(b * SEQ + r1)) * D_MODEL + h * 64;
    #pragma unroll
    for (int nt = 0; nt < 8; nt++) {
        int c0 = nt * 8 + tig * 2;
        *(float2*)&o[ob0 + c0] = make_float2(oacc[nt][0] * i0, oacc[nt][1] * i0);
        *(float2*)&o[ob1 + c0] = make_float2(oacc[nt][2] * i1, oacc[nt][3] * i1);
    }
}

// ---------------- SwiGLU elementwise: u <- u*sigmoid(u)*g ----------------
__global__ void swiglu_k(float* __restrict__ u, const float* __restrict__ g) {
    size_t i = (size_t)blockIdx.x * blockDim.x + threadIdx.x;
    if (i < (size_t)BSROWS * D_FF) {
        float uv = u[i];
        float sg = 1.f / (1.f + __expf(-uv));
        u[i] = uv * sg * g[i];
    }
}

// ---------------- launch ----------------
extern "C" void kernel_launch(void* const* d_in, const int* in_sizes, int n_in,
                              void* d_out, int out_size) {
    const float* x      = (const float*)d_in[0];
    const float* gains1 = (const float*)d_in[1];
    const float* gains2 = (const float*)d_in[2];
    const float* WQ     = (const float*)d_in[3];
    const float* WK     = (const float*)d_in[4];
    const float* WV     = (const float*)d_in[5];
    const float* WO     = (const float*)d_in[6];
    const float* W1     = (const float*)d_in[7];
    const float* W2     = (const float*)d_in[8];
    const float* W3     = (const float*)d_in[9];
    float* out = (float*)d_out;

    float *h, *q, *k, *v, *attn, *y, *u, *g;
    cudaGetSymbolAddress((void**)&h,    g_h);
    cudaGetSymbolAddress((void**)&q,    g_q);
    cudaGetSymbolAddress((void**)&k,    g_k);
    cudaGetSymbolAddress((void**)&v,    g_v);
    cudaGetSymbolAddress((void**)&attn, g_attn);
    cudaGetSymbolAddress((void**)&y,    g_y);
    cudaGetSymbolAddress((void**)&u,    g_u);
    cudaGetSymbolAddress((void**)&g,    g_g);

    // 1. pre-attention RMSNorm
    rmsnorm_k<<<BSROWS, 256>>>(x, gains1, h);

    // 2. QKV projections (TF32 tensor cores)
    dim3 gqkv(D_MODEL / 128, BSROWS / 128);
    gemm_tf32<<<gqkv, 256>>>(h, WQ, nullptr, q, BSROWS, D_MODEL, D_MODEL);
    gemm_tf32<<<gqkv, 256>>>(h, WK, nullptr, k, BSROWS, D_MODEL, D_MODEL);
    gemm_tf32<<<gqkv, 256>>>(h, WV, nullptr, v, BSROWS, D_MODEL, D_MODEL);

    // 3. RoPE on q, k
    int ropeN = BSROWS * (D_MODEL / 2);
    rope_k<<<(ropeN + 255) / 256, 256>>>(q);
    rope_k<<<(ropeN + 255) / 256, 256>>>(k);

    // 4. causal flash attention (TF32 tensor cores)
    cudaFuncSetAttribute(attn_mma, cudaFuncAttributeMaxDynamicSharedMemorySize, ATTN_SMEM);
    attn_mma<<<dim3(SEQ / 128, BATCH * NHEADS), 256, ATTN_SMEM>>>(q, k, v, attn);

    // 5. output projection + residual
    gemm_tf32<<<gqkv, 256>>>(attn, WO, x, y, BSROWS, D_MODEL, D_MODEL);

    // 6. pre-FFN RMSNorm
    rmsnorm_k<<<BSROWS, 256>>>(y, gains2, h);

    // 7. FFN up/gate
    dim3 gff(D_FF / 128, BSROWS / 128);
    gemm_tf32<<<gff, 256>>>(h, W1, nullptr, u, BSROWS, D_FF, D_MODEL);
    gemm_tf32<<<gff, 256>>>(h, W3, nullptr, g, BSROWS, D_FF, D_MODEL);

    // 8. SwiGLU
    size_t nsw = (size_t)BSROWS * D_FF;
    swiglu_k<<<(int)((nsw + 255) / 256), 256>>>(u, g);

    // 9. down projection + residual -> out
    gemm_tf32<<<gqkv, 256>>>(u, W2, y, out, BSROWS, D_MODEL, D_FF);
}

// round 12
// speedup vs baseline: 6.5529x; 1.3045x over previous
#include <cuda_runtime.h>
#include <math.h>

#define D_MODEL 1024
#define D_FF    2816
#define NHEADS  16
#define DK      64
#define BATCH   2
#define SEQ     2048
#define BSROWS  (BATCH*SEQ)   // 4096
#define EPSV    1e-5f

// ---------------- scratch (no cudaMalloc allowed) ----------------
static __device__ float g_h   [(size_t)BSROWS*D_MODEL];
static __device__ float g_q   [(size_t)BSROWS*D_MODEL];
static __device__ float g_k   [(size_t)BSROWS*D_MODEL];
static __device__ float g_v   [(size_t)BSROWS*D_MODEL];
static __device__ float g_attn[(size_t)BSROWS*D_MODEL];
static __device__ float g_y   [(size_t)BSROWS*D_MODEL];
static __device__ float g_u   [(size_t)BSROWS*D_FF];
static __device__ float g_g   [(size_t)BSROWS*D_FF];

// ---------------- common MMA helpers ----------------
__device__ __forceinline__ unsigned f2tf32(float f) {
    unsigned u;
    asm("cvt.rna.tf32.f32 %0, %1;\n" : "=r"(u) : "f"(f));
    return u;
}

__device__ __forceinline__ void mma_tf32(float* d, const unsigned* a, const unsigned* b) {
    asm volatile(
        "mma.sync.aligned.m16n8k8.row.col.f32.tf32.tf32.f32 "
        "{%0,%1,%2,%3}, {%4,%5,%6,%7}, {%8,%9}, {%0,%1,%2,%3};\n"
        : "+f"(d[0]), "+f"(d[1]), "+f"(d[2]), "+f"(d[3])
        : "r"(a[0]), "r"(a[1]), "r"(a[2]), "r"(a[3]), "r"(b[0]), "r"(b[1]));
}

__device__ __forceinline__ void cp_a16(unsigned d, const float* s) {
    asm volatile("cp.async.cg.shared.global [%0], [%1], 16;\n" :: "r"(d), "l"(s));
}

// ---------------- RMSNorm: one block per row ----------------
__global__ void rmsnorm_k(const float* __restrict__ x, const float* __restrict__ gains,
                          float* __restrict__ o) {
    int row = blockIdx.x;
    const float* xr = x + (size_t)row * D_MODEL;
    float*       orow = o + (size_t)row * D_MODEL;
    float s = 0.f;
    for (int i = threadIdx.x; i < D_MODEL; i += 256) { float v = xr[i]; s += v * v; }
    #pragma unroll
    for (int off = 16; off; off >>= 1) s += __shfl_xor_sync(0xffffffffu, s, off);
    __shared__ float ws[8];
    __shared__ float rinv;
    if ((threadIdx.x & 31) == 0) ws[threadIdx.x >> 5] = s;
    __syncthreads();
    if (threadIdx.x == 0) {
        float t = 0.f;
        #pragma unroll
        for (int i = 0; i < 8; i++) t += ws[i];
        rinv = rsqrtf(t / (float)D_MODEL + EPSV);
    }
    __syncthreads();
    float r = rinv;
    for (int i = threadIdx.x; i < D_MODEL; i += 256)
        orow[i] = xr[i] * gains[i] * r;
}

// ---------------- TF32 GEMM core: cp.async 2-stage, K-chunk 32 ----------------
// C[128,128 tile] = A[M,K] * B[N,K]^T (+res / rope). fp32 bits fed directly to
// mma.tf32 (HW RZ truncation). Smem row stride 36 words -> conflict-free frags.
#define KSTG (128 * 36)                 // words per matrix per stage
#define GEMM_SMEM (4 * KSTG * 4)        // 73728 bytes

__device__ __forceinline__ void gemm_core(const float* __restrict__ A,
                                          const float* __restrict__ B,
                                          const float* __restrict__ res,
                                          float* __restrict__ C,
                                          int N, int K, int bm, int bn, int rope) {
    extern __shared__ unsigned smg[];
    const int t = threadIdx.x;
    const int warp = t >> 5, lane = t & 31;
    const int gid = lane >> 2, tig = lane & 3;
    const int wm = (warp >> 2) * 64, wn = (warp & 3) * 32;

    const int arow = t >> 3;         // 0..31
    const int ac4  = (t & 7) * 4;    // 0..28
    const float* Ag = A + (size_t)(bm + arow) * K + ac4;
    const float* Bg = B + (size_t)(bn + arow) * K + ac4;
    unsigned sbase = (unsigned)__cvta_generic_to_shared(smg);

    auto issue = [&](int s, int kof) {
        unsigned abase = sbase + (unsigned)(s * 2 * KSTG) * 4u;
        unsigned bbase = abase + (unsigned)KSTG * 4u;
        #pragma unroll
        for (int i = 0; i < 4; i++) {
            unsigned off = (unsigned)((arow + i * 32) * 36 + ac4) * 4u;
            cp_a16(abase + off, Ag + (size_t)(i * 32) * K + kof);
            cp_a16(bbase + off, Bg + (size_t)(i * 32) * K + kof);
        }
        asm volatile("cp.async.commit_group;\n" ::: "memory");
    };

    float acc[4][4][4];
    #pragma unroll
    for (int i = 0; i < 4; i++)
        #pragma unroll
        for (int j = 0; j < 4; j++)
            #pragma unroll
            for (int r = 0; r < 4; r++) acc[i][j][r] = 0.f;

    issue(0, 0);
    const int T = K >> 5;
    for (int kt = 0; kt < T; kt++) {
        asm volatile("cp.async.wait_group 0;\n" ::: "memory");
        __syncthreads();   // stage kt visible; all warps done with stage kt-1
        if (kt + 1 < T) issue((kt + 1) & 1, (kt + 1) * 32);
        const unsigned* As = smg + (kt & 1) * 2 * KSTG;
        const unsigned* Bs = As + KSTG;
        #pragma unroll
        for (int ks = 0; ks < 4; ks++) {
            const int ko = ks * 8;
            unsigned af[4][4];
            #pragma unroll
            for (int mt = 0; mt < 4; mt++) {
                int r = wm + mt * 16 + gid;
                af[mt][0] = As[r * 36 + ko + tig];
                af[mt][1] = As[(r + 8) * 36 + ko + tig];
                af[mt][2] = As[r * 36 + ko + tig + 4];
                af[mt][3] = As[(r + 8) * 36 + ko + tig + 4];
            }
            unsigned bf[4][2];
            #pragma unroll
            for (int nt = 0; nt < 4; nt++) {
                int c = wn + nt * 8 + gid;
                bf[nt][0] = Bs[c * 36 + ko + tig];
                bf[nt][1] = Bs[c * 36 + ko + tig + 4];
            }
            #pragma unroll
            for (int mt = 0; mt < 4; mt++)
                #pragma unroll
                for (int nt = 0; nt < 4; nt++)
                    mma_tf32(acc[mt][nt], af[mt], bf[nt]);
        }
    }

    // epilogue
    #pragma unroll
    for (int mt = 0; mt < 4; mt++) {
        int r0 = bm + wm + mt * 16 + gid;
        #pragma unroll
        for (int nt = 0; nt < 4; nt++) {
            int c0 = bn + wn + nt * 8 + tig * 2;
            float2 v0 = make_float2(acc[mt][nt][0], acc[mt][nt][1]);
            float2 v1 = make_float2(acc[mt][nt][2], acc[mt][nt][3]);
            if (rope) {
                int d = c0 & 63;   // even; pair (d, d+1), j = d/2
                float inv = expf(-(float)d * (9.210340371976184f / 64.f));
                float sn0, cs0, sn1, cs1;
                sincosf((float)(r0 & (SEQ - 1)) * inv, &sn0, &cs0);
                sincosf((float)((r0 + 8) & (SEQ - 1)) * inv, &sn1, &cs1);
                float t0 = v0.x * cs0 - v0.y * sn0;
                v0.y = v0.y * cs0 + v0.x * sn0; v0.x = t0;
                float t1 = v1.x * cs1 - v1.y * sn1;
                v1.y = v1.y * cs1 + v1.x * sn1; v1.x = t1;
            } else if (res) {
                float2 r0v = *(const float2*)&res[(size_t)r0 * N + c0];
                float2 r1v = *(const float2*)&res[(size_t)(r0 + 8) * N + c0];
                v0.x += r0v.x; v0.y += r0v.y;
                v1.x += r1v.x; v1.y += r1v.y;
            }
            *(float2*)&C[(size_t)r0 * N + c0]       = v0;
            *(float2*)&C[(size_t)(r0 + 8) * N + c0] = v1;
        }
    }
}

__global__ __launch_bounds__(256, 2) void gemm_plain(const float* __restrict__ A,
                                                     const float* __restrict__ B,
                                                     const float* __restrict__ res,
                                                     float* __restrict__ C,
                                                     int N, int K) {
    gemm_core(A, B, res, C, N, K, blockIdx.y * 128, blockIdx.x * 128, 0);
}

// fused QKV: grid.x = 24 (8 per matrix); RoPE fused for Q,K
__global__ __launch_bounds__(256, 2) void gemm_qkv(const float* __restrict__ A,
                                                   const float* __restrict__ WQ,
                                                   const float* __restrict__ WK,
                                                   const float* __restrict__ WV,
                                                   float* __restrict__ q,
                                                   float* __restrict__ k,
                                                   float* __restrict__ v) {
    int sel = blockIdx.x >> 3;
    const float* B = (sel == 0) ? WQ : (sel == 1) ? WK : WV;
    float* C       = (sel == 0) ? q  : (sel == 1) ? k  : v;
    gemm_core(A, B, nullptr, C, D_MODEL, D_MODEL,
              blockIdx.y * 128, (blockIdx.x & 7) * 128, sel < 2);
}

// fused FFN up/gate: grid.x = 44 (22 per matrix)
__global__ __launch_bounds__(256, 2) void gemm_ug(const float* __restrict__ A,
                                                  const float* __restrict__ W1,
                                                  const float* __restrict__ W3,
                                                  float* __restrict__ u,
                                                  float* __restrict__ g) {
    int sel = (blockIdx.x >= 22);
    gemm_core(A, sel ? W3 : W1, nullptr, sel ? g : u, D_FF, D_MODEL,
              blockIdx.y * 128, (blockIdx.x - sel * 22) * 128, 0);
}

// ---------------- Flash attention, TF32 tensor cores (unchanged from R11) ----------------
#define ASTR 68
#define ATTN_SMEM ((128 * ASTR + 2 * 64 * ASTR) * 4)
__global__ __launch_bounds__(256) void attn_mma(const float* __restrict__ q,
                                                const float* __restrict__ k,
                                                const float* __restrict__ v,
                                                float* __restrict__ o) {
    extern __shared__ unsigned sm_u[];
    unsigned* Qs = sm_u;
    unsigned* Ps = sm_u;
    unsigned* Ks = sm_u + 128 * ASTR;
    unsigned* Vs = Ks + 64 * ASTR;

    const int bh = blockIdx.y;
    const int b  = bh / NHEADS, h = bh % NHEADS;
    const int q0 = blockIdx.x * 128;
    const int t  = threadIdx.x;
    const int warp = t >> 5, lane = t & 31;
    const int gid = lane >> 2, tig = lane & 3;
    const int wr  = warp * 16;

    for (int i = t; i < 128 * 16; i += 256) {
        int r = i >> 4, d4 = i & 15;
        float4 qv = *(const float4*)&q[((size_t)(b * SEQ + q0 + r)) * D_MODEL + h * 64 + d4 * 4];
        *(uint4*)&Qs[r * ASTR + d4 * 4] =
            make_uint4(f2tf32(qv.x * 0.125f), f2tf32(qv.y * 0.125f),
                       f2tf32(qv.z * 0.125f), f2tf32(qv.w * 0.125f));
    }
    __syncthreads();

    unsigned qa[8][4];
    #pragma unroll
    for (int ks = 0; ks < 8; ks++) {
        qa[ks][0] = Qs[(wr + gid) * ASTR + ks * 8 + tig];
        qa[ks][1] = Qs[(wr + gid + 8) * ASTR + ks * 8 + tig];
        qa[ks][2] = Qs[(wr + gid) * ASTR + ks * 8 + tig + 4];
        qa[ks][3] = Qs[(wr + gid + 8) * ASTR + ks * 8 + tig + 4];
    }

    float oacc[8][4];
    #pragma unroll
    for (int nt = 0; nt < 8; nt++)
        #pragma unroll
        for (int e = 0; e < 4; e++) oacc[nt][e] = 0.f;
    float m0 = -1e30f, m1 = -1e30f, l0 = 0.f, l1 = 0.f;

    const int r0 = q0 + wr + gid;
    const int r1 = r0 + 8;
    const int ntiles = q0 / 64 + 2;

    for (int kt = 0; kt < ntiles; kt++) {
        const int k0 = kt * 64;
        __syncthreads();
        for (int i = t; i < 64 * 16; i += 256) {
            int r = i >> 4, d4 = i & 15;
            size_t gi = ((size_t)(b * SEQ + k0 + r)) * D_MODEL + h * 64 + d4 * 4;
            float4 kv = *(const float4*)&k[gi];
            *(uint4*)&Ks[r * ASTR + d4 * 4] =
                make_uint4(f2tf32(kv.x), f2tf32(kv.y), f2tf32(kv.z), f2tf32(kv.w));
            float4 vv = *(const float4*)&v[gi];
            Vs[(d4 * 4 + 0) * ASTR + r] = f2tf32(vv.x);
            Vs[(d4 * 4 + 1) * ASTR + r] = f2tf32(vv.y);
            Vs[(d4 * 4 + 2) * ASTR + r] = f2tf32(vv.z);
            Vs[(d4 * 4 + 3) * ASTR + r] = f2tf32(vv.w);
        }
        __syncthreads();

        float sacc[8][4];
        #pragma unroll
        for (int nt = 0; nt < 8; nt++) {
            sacc[nt][0] = sacc[nt][1] = sacc[nt][2] = sacc[nt][3] = 0.f;
            #pragma unroll
            for (int ks = 0; ks < 8; ks++) {
                unsigned kb[2];
                kb[0] = Ks[(nt * 8 + gid) * ASTR + ks * 8 + tig];
                kb[1] = Ks[(nt * 8 + gid) * ASTR + ks * 8 + tig + 4];
                mma_tf32(sacc[nt], qa[ks], kb);
            }
        }

        if (k0 + 63 > q0) {
            #pragma unroll
            for (int nt = 0; nt < 8; nt++) {
                int c0 = k0 + nt * 8 + tig * 2;
                if (c0     > r0) sacc[nt][0] = -1e30f;
                if (c0 + 1 > r0) sacc[nt][1] = -1e30f;
                if (c0     > r1) sacc[nt][2] = -1e30f;
                if (c0 + 1 > r1) sacc[nt][3] = -1e30f;
            }
        }

        float m0loc = -1e30f, m1loc = -1e30f;
        #pragma unroll
        for (int nt = 0; nt < 8; nt++) {
            m0loc = fmaxf(m0loc, fmaxf(sacc[nt][0], sacc[nt][1]));
            m1loc = fmaxf(m1loc, fmaxf(sacc[nt][2], sacc[nt][3]));
        }
        m0loc = fmaxf(m0loc, __shfl_xor_sync(0xffffffffu, m0loc, 1));
        m0loc = fmaxf(m0loc, __shfl_xor_sync(0xffffffffu, m0loc, 2));
        m1loc = fmaxf(m1loc, __shfl_xor_sync(0xffffffffu, m1loc, 1));
        m1loc = fmaxf(m1loc, __shfl_xor_sync(0xffffffffu, m1loc, 2));
        float mn0 = fmaxf(m0, m0loc), mn1 = fmaxf(m1, m1loc);
        float corr0 = __expf(m0 - mn0), corr1 = __expf(m1 - mn1);
        float ps0 = 0.f, ps1 = 0.f;
        #pragma unroll
        for (int nt = 0; nt < 8; nt++) {
            float p0 = __expf(sacc[nt][0] - mn0);
            float p1 = __expf(sacc[nt][1] - mn0);
            float p2 = __expf(sacc[nt][2] - mn1);
            float p3 = __expf(sacc[nt][3] - mn1);
            ps0 += p0 + p1; ps1 += p2 + p3;
            *(uint2*)&Ps[(wr + gid) * ASTR + nt * 8 + tig * 2] =
                make_uint2(f2tf32(p0), f2tf32(p1));
            *(uint2*)&Ps[(wr + gid + 8) * ASTR + nt * 8 + tig * 2] =
                make_uint2(f2tf32(p2), f2tf32(p3));
        }
        ps0 += __shfl_xor_sync(0xffffffffu, ps0, 1);
        ps0 += __shfl_xor_sync(0xffffffffu, ps0, 2);
        ps1 += __shfl_xor_sync(0xffffffffu, ps1, 1);
        ps1 += __shfl_xor_sync(0xffffffffu, ps1, 2);
        l0 = l0 * corr0 + ps0;
        l1 = l1 * corr1 + ps1;
        m0 = mn0; m1 = mn1;
        #pragma unroll
        for (int nt = 0; nt < 8; nt++) {
            oacc[nt][0] *= corr0; oacc[nt][1] *= corr0;
            oacc[nt][2] *= corr1; oacc[nt][3] *= corr1;
        }
        __syncwarp();

        #pragma unroll
        for (int ks = 0; ks < 8; ks++) {
            unsigned pa[4];
            pa[0] = Ps[(wr + gid) * ASTR + ks * 8 + tig];
            pa[1] = Ps[(wr + gid + 8) * ASTR + ks * 8 + tig];
            pa[2] = Ps[(wr + gid) * ASTR + ks * 8 + tig + 4];
            pa[3] = Ps[(wr + gid + 8) * ASTR + ks * 8 + tig + 4];
            #pragma unroll
            for (int nt = 0; nt < 8; nt++) {
                unsigned vb[2];
                vb[0] = Vs[(nt * 8 + gid) * ASTR + ks * 8 + tig];
                vb[1] = Vs[(nt * 8 + gid) * ASTR + ks * 8 + tig + 4];
                mma_tf32(oacc[nt], pa, vb);
            }
        }
    }

    float i0 = 1.f / l0, i1 = 1.f / l1;
    size_t ob0 = ((size_t)(b * SEQ + r0)) * D_MODEL + h * 64;
    size_t ob1 = ((size_t)(b * SEQ + r1)) * D_MODEL + h * 64;
    #pragma unroll
    for (int nt = 0; nt < 8; nt++) {
        int c0 = nt * 8 + tig * 2;
        *(float2*)&o[ob0 + c0] = make_float2(oacc[nt][0] * i0, oacc[nt][1] * i0);
        *(float2*)&o[ob1 + c0] = make_float2(oacc[nt][2] * i1, oacc[nt][3] * i1);
    }
}

// ---------------- SwiGLU elementwise: u <- u*sigmoid(u)*g ----------------
__global__ void swiglu_k(float* __restrict__ u, const float* __restrict__ g) {
    size_t i = (size_t)blockIdx.x * blockDim.x + threadIdx.x;
    if (i < (size_t)BSROWS * D_FF) {
        float uv = u[i];
        float sg = 1.f / (1.f + __expf(-uv));
        u[i] = uv * sg * g[i];
    }
}

// ---------------- launch ----------------
extern "C" void kernel_launch(void* const* d_in, const int* in_sizes, int n_in,
                              void* d_out, int out_size) {
    const float* x      = (const float*)d_in[0];
    const float* gains1 = (const float*)d_in[1];
    const float* gains2 = (const float*)d_in[2];
    const float* WQ     = (const float*)d_in[3];
    const float* WK     = (const float*)d_in[4];
    const float* WV     = (const float*)d_in[5];
    const float* WO     = (const float*)d_in[6];
    const float* W1     = (const float*)d_in[7];
    const float* W2     = (const float*)d_in[8];
    const float* W3     = (const float*)d_in[9];
    float* out = (float*)d_out;

    float *h, *q, *k, *v, *attn, *y, *u, *g;
    cudaGetSymbolAddress((void**)&h,    g_h);
    cudaGetSymbolAddress((void**)&q,    g_q);
    cudaGetSymbolAddress((void**)&k,    g_k);
    cudaGetSymbolAddress((void**)&v,    g_v);
    cudaGetSymbolAddress((void**)&attn, g_attn);
    cudaGetSymbolAddress((void**)&y,    g_y);
    cudaGetSymbolAddress((void**)&u,    g_u);
    cudaGetSymbolAddress((void**)&g,    g_g);

    cudaFuncSetAttribute(gemm_plain, cudaFuncAttributeMaxDynamicSharedMemorySize, GEMM_SMEM);
    cudaFuncSetAttribute(gemm_qkv,   cudaFuncAttributeMaxDynamicSharedMemorySize, GEMM_SMEM);
    cudaFuncSetAttribute(gemm_ug,    cudaFuncAttributeMaxDynamicSharedMemorySize, GEMM_SMEM);
    cudaFuncSetAttribute(attn_mma,   cudaFuncAttributeMaxDynamicSharedMemorySize, ATTN_SMEM);

    // 1. pre-attention RMSNorm
    rmsnorm_k<<<BSROWS, 256>>>(x, gains1, h);

    // 2. QKV projections + fused RoPE (one launch)
    gemm_qkv<<<dim3(24, BSROWS / 128), 256, GEMM_SMEM>>>(h, WQ, WK, WV, q, k, v);

    // 3. causal flash attention (TF32 tensor cores)
    attn_mma<<<dim3(SEQ / 128, BATCH * NHEADS), 256, ATTN_SMEM>>>(q, k, v, attn);

    // 4. output projection + residual
    gemm_plain<<<dim3(D_MODEL / 128, BSROWS / 128), 256, GEMM_SMEM>>>(
        attn, WO, x, y, D_MODEL, D_MODEL);

    // 5. pre-FFN RMSNorm
    rmsnorm_k<<<BSROWS, 256>>>(y, gains2, h);

    // 6. FFN up + gate (one launch)
    gemm_ug<<<dim3(44, BSROWS / 128), 256, GEMM_SMEM>>>(h, W1, W3, u, g);

    // 7. SwiGLU
    size_t nsw = (size_t)BSROWS * D_FF;
    swiglu_k<<<(int)((nsw + 255) / 256), 256>>>(u, g);

    // 8. down projection + residual -> out
    gemm_plain<<<dim3(D_MODEL / 128, BSROWS / 128), 256, GEMM_SMEM>>>(
        u, W2, y, out, D_MODEL, D_FF);
}